// round 1
// baseline (speedup 1.0000x reference)
#include <cuda_runtime.h>
#include <cuda_bf16.h>

// ---------------- problem constants ----------------
#define BB 2
#define SS 2048
#define DD 3584
#define HH 28
#define KVH 4
#define HDIM 128
#define NREP 7
#define MM (BB*SS)            // 4096
#define QK_SCALE 0.08838834764831845f

// ---------------- scratch (static device, no allocs) ----------------
__device__ float g_q[(size_t)MM * DD];          // [4096][3584]
__device__ float g_k[(size_t)MM * (KVH*HDIM)];  // [4096][512]
__device__ float g_v[(size_t)MM * (KVH*HDIM)];  // [4096][512]
__device__ float g_o[(size_t)MM * DD];          // [4096][3584]

// =====================================================================
// Generic TN SGEMM tile: C[128,128] = A[128,K] * W[128,K]^T (+bias)
// 256 threads, 8x8 microtile, BK=8, float4 fragments, prefetch regs.
// =====================================================================
__device__ __forceinline__ void gemm_tn_tile(
    const float* __restrict__ A, int lda,      // points at (m0, 0)
    const float* __restrict__ W,               // points at (n0, 0), ld = K
    const float* __restrict__ bias,            // points at n0, or null
    float* __restrict__ C, int ldc,            // points at (m0, n0)
    int K)
{
    __shared__ __align__(16) float As[8][132];
    __shared__ __align__(16) float Bs[8][132];
    const int tid = threadIdx.x;
    const int ty = tid >> 4, tx = tid & 15;
    const int lrow = tid >> 1;
    const int lk = (tid & 1) << 2;

    const float* Ap = A + lrow * lda + lk;
    const float* Wp = W + lrow * K + lk;

    float acc[8][8];
#pragma unroll
    for (int i = 0; i < 8; i++)
#pragma unroll
        for (int j = 0; j < 8; j++) acc[i][j] = 0.f;

    float4 a4 = *(const float4*)Ap;
    float4 w4 = *(const float4*)Wp;

    for (int k0 = 0; k0 < K; k0 += 8) {
        __syncthreads();
        As[lk+0][lrow] = a4.x; As[lk+1][lrow] = a4.y;
        As[lk+2][lrow] = a4.z; As[lk+3][lrow] = a4.w;
        Bs[lk+0][lrow] = w4.x; Bs[lk+1][lrow] = w4.y;
        Bs[lk+2][lrow] = w4.z; Bs[lk+3][lrow] = w4.w;
        __syncthreads();
        if (k0 + 8 < K) {                 // prefetch next K-slab
            a4 = *(const float4*)(Ap + k0 + 8);
            w4 = *(const float4*)(Wp + k0 + 8);
        }
#pragma unroll
        for (int kk = 0; kk < 8; kk++) {
            float4 x0 = *(const float4*)&As[kk][ty*4];
            float4 x1 = *(const float4*)&As[kk][64 + ty*4];
            float4 y0 = *(const float4*)&Bs[kk][tx*4];
            float4 y1 = *(const float4*)&Bs[kk][64 + tx*4];
            float av[8] = {x0.x,x0.y,x0.z,x0.w, x1.x,x1.y,x1.z,x1.w};
            float bv[8] = {y0.x,y0.y,y0.z,y0.w, y1.x,y1.y,y1.z,y1.w};
#pragma unroll
            for (int i = 0; i < 8; i++)
#pragma unroll
                for (int j = 0; j < 8; j++)
                    acc[i][j] = fmaf(av[i], bv[j], acc[i][j]);
        }
    }

    float bvals[8];
#pragma unroll
    for (int j = 0; j < 8; j++) {
        int c = (j < 4) ? (tx*4 + j) : (64 + tx*4 + (j - 4));
        bvals[j] = bias ? bias[c] : 0.f;
    }
#pragma unroll
    for (int i = 0; i < 8; i++) {
        int r = (i < 4) ? (ty*4 + i) : (64 + ty*4 + (i - 4));
        float4 o0 = make_float4(acc[i][0]+bvals[0], acc[i][1]+bvals[1],
                                acc[i][2]+bvals[2], acc[i][3]+bvals[3]);
        float4 o1 = make_float4(acc[i][4]+bvals[4], acc[i][5]+bvals[5],
                                acc[i][6]+bvals[6], acc[i][7]+bvals[7]);
        *(float4*)(C + r*ldc + tx*4)      = o0;
        *(float4*)(C + r*ldc + 64 + tx*4) = o1;
    }
}

// Fused QKV projection: grid (32, 36). by<28 -> Q, <32 -> K, else V.
__global__ __launch_bounds__(256) void qkv_kernel(
    const float* __restrict__ x,
    const float* __restrict__ wq, const float* __restrict__ bq,
    const float* __restrict__ wk, const float* __restrict__ bk,
    const float* __restrict__ wv, const float* __restrict__ bv)
{
    int m0 = blockIdx.x * 128;
    int by = blockIdx.y;
    const float* W; const float* bias; float* C; int ldc;
    if (by < 28) {
        W = wq + by * 128 * DD;  bias = bq + by * 128;
        C = g_q + (size_t)m0 * DD + by * 128; ldc = DD;
    } else if (by < 32) {
        int nb = by - 28;
        W = wk + nb * 128 * DD;  bias = bk + nb * 128;
        C = g_k + (size_t)m0 * 512 + nb * 128; ldc = 512;
    } else {
        int nb = by - 32;
        W = wv + nb * 128 * DD;  bias = bv + nb * 128;
        C = g_v + (size_t)m0 * 512 + nb * 128; ldc = 512;
    }
    gemm_tn_tile(x + (size_t)m0 * DD, DD, W, bias, C, ldc, DD);
}

// Output projection: grid (32, 28).
__global__ __launch_bounds__(256) void oproj_kernel(
    const float* __restrict__ wo, float* __restrict__ out)
{
    int m0 = blockIdx.x * 128;
    int n0 = blockIdx.y * 128;
    gemm_tn_tile(g_o + (size_t)m0 * DD, DD, wo + (size_t)n0 * DD, nullptr,
                 out + (size_t)m0 * DD + n0, DD, DD);
}

// =====================================================================
// RoPE on g_q and g_k (in place). One thread per (row, head, dim-pair).
// =====================================================================
__global__ __launch_bounds__(256) void rope_kernel(
    const float* __restrict__ cosT, const float* __restrict__ sinT,
    const int* __restrict__ spp)
{
    const int QP = MM * HH * 64;         // 7,340,032
    const int KP = MM * KVH * 64;        // 1,048,576
    int idx = blockIdx.x * blockDim.x + threadIdx.x;
    if (idx >= QP + KP) return;
    int sp = spp[0];
    float* buf; int nh; int i2;
    if (idx < QP) { buf = g_q; nh = HH;  i2 = idx; }
    else          { buf = g_k; nh = KVH; i2 = idx - QP; }
    int d2 = i2 & 63;
    int t  = i2 >> 6;               // m*nh + h
    int h  = t % nh;
    int m  = t / nh;
    int s  = m & (SS - 1);          // m % S
    int pos = sp + s;
    float c  = cosT[pos * 64 + d2];
    float sn = sinT[pos * 64 + d2];
    size_t off = (size_t)m * (nh * HDIM) + h * HDIM + 2 * d2;
    float2 v = *(float2*)(buf + off);
    float yr = v.x * c - v.y * sn;
    float yi = v.x * sn + v.y * c;
    *(float2*)(buf + off) = make_float2(yr, yi);
}

// =====================================================================
// Flash attention (causal), fp32. BM=BN=64, HD=128, 256 threads (16x16),
// 4x4 S-microtile, online softmax. Dynamic smem ~117 KB.
// grid: (32 q-tiles [reversed], 28 heads, 2 batches)
// =====================================================================
#define ATTN_SMEM_FLOATS (2*128*68 + 64*128 + 64*68)

__global__ __launch_bounds__(256) void attn_kernel()
{
    extern __shared__ float sm[];
    float* Qt = sm;                        // [128][68]  (d-major, transposed)
    float* Kt = sm + 128*68;               // [128][68]
    float* Vs = sm + 2*128*68;             // [64][128]  (row-major)
    float* Ps = sm + 2*128*68 + 64*128;    // [64][68]

    const int qt = gridDim.x - 1 - blockIdx.x;   // heavy tiles first
    const int h  = blockIdx.y;
    const int b  = blockIdx.z;
    const int kvh = h / NREP;
    const int tid = threadIdx.x;
    const int ty = tid >> 4, tx = tid & 15;

    const int qrow0 = b * SS + qt * 64;

    // ---- load Q tile (64x128) transposed into Qt ----
    {
        const float* qbase = g_q + (size_t)qrow0 * DD + h * HDIM;
#pragma unroll
        for (int t = 0; t < 8; t++) {
            int f4 = tid + t * 256;
            int row = f4 >> 5, d4 = f4 & 31;
            float4 qv = *(const float4*)(qbase + (size_t)row * DD + d4 * 4);
            Qt[(d4*4+0)*68 + row] = qv.x;
            Qt[(d4*4+1)*68 + row] = qv.y;
            Qt[(d4*4+2)*68 + row] = qv.z;
            Qt[(d4*4+3)*68 + row] = qv.w;
        }
    }

    float m_i[4], l_i[4], o_acc[4][8];
#pragma unroll
    for (int i = 0; i < 4; i++) {
        m_i[i] = -1e30f; l_i[i] = 0.f;
#pragma unroll
        for (int c = 0; c < 8; c++) o_acc[i][c] = 0.f;
    }

    for (int nt = 0; nt <= qt; nt++) {
        const int n0 = nt * 64;
        const float* kbase = g_k + (size_t)(b * SS + n0) * 512 + kvh * HDIM;
        const float* vbase = g_v + (size_t)(b * SS + n0) * 512 + kvh * HDIM;

        __syncthreads();   // previous iter finished reading Kt/Vs/Ps (covers Q load too)
#pragma unroll
        for (int t = 0; t < 8; t++) {
            int f4 = tid + t * 256;
            int row = f4 >> 5, d4 = f4 & 31;
            float4 kv4 = *(const float4*)(kbase + (size_t)row * 512 + d4 * 4);
            Kt[(d4*4+0)*68 + row] = kv4.x;
            Kt[(d4*4+1)*68 + row] = kv4.y;
            Kt[(d4*4+2)*68 + row] = kv4.z;
            Kt[(d4*4+3)*68 + row] = kv4.w;
            float4 vv4 = *(const float4*)(vbase + (size_t)row * 512 + d4 * 4);
            *(float4*)&Vs[row * 128 + d4 * 4] = vv4;
        }
        __syncthreads();

        // ---- S = Q K^T (64x64x128) ----
        float s[4][4];
#pragma unroll
        for (int i = 0; i < 4; i++)
#pragma unroll
            for (int j = 0; j < 4; j++) s[i][j] = 0.f;

#pragma unroll 4
        for (int d = 0; d < 128; d++) {
            float4 q4 = *(const float4*)&Qt[d*68 + ty*4];
            float4 k4 = *(const float4*)&Kt[d*68 + tx*4];
            float qa[4] = {q4.x, q4.y, q4.z, q4.w};
            float ka[4] = {k4.x, k4.y, k4.z, k4.w};
#pragma unroll
            for (int i = 0; i < 4; i++)
#pragma unroll
                for (int j = 0; j < 4; j++)
                    s[i][j] = fmaf(qa[i], ka[j], s[i][j]);
        }

        const bool diag = (nt == qt);

        // ---- online softmax update (per row, 16-lane shuffle reductions) ----
#pragma unroll
        for (int i = 0; i < 4; i++) {
#pragma unroll
            for (int j = 0; j < 4; j++) {
                float val = s[i][j] * QK_SCALE;
                if (diag && (tx*4 + j > ty*4 + i)) val = -1e30f;
                s[i][j] = val;
            }
            float mt = fmaxf(fmaxf(s[i][0], s[i][1]), fmaxf(s[i][2], s[i][3]));
#pragma unroll
            for (int off = 8; off > 0; off >>= 1)
                mt = fmaxf(mt, __shfl_xor_sync(0xffffffffu, mt, off));
            float mnew  = fmaxf(m_i[i], mt);
            float alpha = __expf(m_i[i] - mnew);
            m_i[i] = mnew;
            float p0 = __expf(s[i][0] - mnew);
            float p1 = __expf(s[i][1] - mnew);
            float p2 = __expf(s[i][2] - mnew);
            float p3 = __expf(s[i][3] - mnew);
            float rs = (p0 + p1) + (p2 + p3);
#pragma unroll
            for (int off = 8; off > 0; off >>= 1)
                rs += __shfl_xor_sync(0xffffffffu, rs, off);
            l_i[i] = l_i[i] * alpha + rs;
#pragma unroll
            for (int c = 0; c < 8; c++) o_acc[i][c] *= alpha;
            int pr = (ty*4 + i) * 68 + tx*4;
            Ps[pr + 0] = p0; Ps[pr + 1] = p1; Ps[pr + 2] = p2; Ps[pr + 3] = p3;
        }
        __syncthreads();

        // ---- O += P V (64x128x64) ----
#pragma unroll 2
        for (int kc = 0; kc < 64; kc++) {
            float4 va = *(const float4*)&Vs[kc*128 + tx*4];
            float4 vb = *(const float4*)&Vs[kc*128 + 64 + tx*4];
#pragma unroll
            for (int i = 0; i < 4; i++) {
                float pp = Ps[(ty*4+i)*68 + kc];
                o_acc[i][0] = fmaf(pp, va.x, o_acc[i][0]);
                o_acc[i][1] = fmaf(pp, va.y, o_acc[i][1]);
                o_acc[i][2] = fmaf(pp, va.z, o_acc[i][2]);
                o_acc[i][3] = fmaf(pp, va.w, o_acc[i][3]);
                o_acc[i][4] = fmaf(pp, vb.x, o_acc[i][4]);
                o_acc[i][5] = fmaf(pp, vb.y, o_acc[i][5]);
                o_acc[i][6] = fmaf(pp, vb.z, o_acc[i][6]);
                o_acc[i][7] = fmaf(pp, vb.w, o_acc[i][7]);
            }
        }
    }

    // ---- epilogue: normalize and write out ----
    float* obase = g_o + (size_t)qrow0 * DD + h * HDIM;
#pragma unroll
    for (int i = 0; i < 4; i++) {
        int r = ty*4 + i;
        float inv = 1.0f / l_i[i];
        float4 r0 = make_float4(o_acc[i][0]*inv, o_acc[i][1]*inv,
                                o_acc[i][2]*inv, o_acc[i][3]*inv);
        float4 r1 = make_float4(o_acc[i][4]*inv, o_acc[i][5]*inv,
                                o_acc[i][6]*inv, o_acc[i][7]*inv);
        *(float4*)(obase + (size_t)r * DD + tx*4)      = r0;
        *(float4*)(obase + (size_t)r * DD + 64 + tx*4) = r1;
    }
}

// =====================================================================
// launch
// =====================================================================
extern "C" void kernel_launch(void* const* d_in, const int* in_sizes, int n_in,
                              void* d_out, int out_size)
{
    const float* x    = (const float*)d_in[0];
    const float* wq_w = (const float*)d_in[1];
    const float* wq_b = (const float*)d_in[2];
    const float* wk_w = (const float*)d_in[3];
    const float* wk_b = (const float*)d_in[4];
    const float* wv_w = (const float*)d_in[5];
    const float* wv_b = (const float*)d_in[6];
    const float* wo_w = (const float*)d_in[7];
    const float* fcos = (const float*)d_in[10];
    const float* fsin = (const float*)d_in[11];
    const int*   spos = (const int*)d_in[13];
    float* out = (float*)d_out;

    size_t attn_smem = (size_t)ATTN_SMEM_FLOATS * sizeof(float);
    cudaFuncSetAttribute(attn_kernel,
                         cudaFuncAttributeMaxDynamicSharedMemorySize,
                         (int)attn_smem);

    qkv_kernel<<<dim3(32, 36), 256>>>(x, wq_w, wq_b, wk_w, wk_b, wv_w, wv_b);

    int pairs = MM * HH * 64 + MM * KVH * 64;   // 8,388,608
    rope_kernel<<<(pairs + 255) / 256, 256>>>(fcos, fsin, spos);

    attn_kernel<<<dim3(32, 28, 2), 256, attn_smem>>>();

    oproj_kernel<<<dim3(32, 28), 256>>>(wo_w, out);
}

// round 2
// speedup vs baseline: 1.5502x; 1.5502x over previous
#include <cuda_runtime.h>
#include <cuda_bf16.h>
#include <cstdint>

// ---------------- problem constants ----------------
#define BB 2
#define SS 2048
#define DD 3584
#define HH 28
#define KVH 4
#define HDIM 128
#define NREP 7
#define MM (BB*SS)            // 4096
#define QK_SCALE 0.08838834764831845f

// ---------------- scratch (static device, no allocs) ----------------
__device__ float g_q[(size_t)MM * DD];          // [4096][3584]
__device__ float g_k[(size_t)MM * (KVH*HDIM)];  // [4096][512]
__device__ float g_v[(size_t)MM * (KVH*HDIM)];  // [4096][512]
__device__ float g_o[(size_t)MM * DD];          // [4096][3584]

// ---------------- helpers ----------------
__device__ __forceinline__ uint32_t f2tf32(float f) {
    uint32_t u;
    asm("cvt.rna.tf32.f32 %0, %1;" : "=r"(u) : "f"(f));
    return u;
}

__device__ __forceinline__ void mma_tf32(float c[4],
                                         uint32_t a0, uint32_t a1, uint32_t a2, uint32_t a3,
                                         uint32_t b0, uint32_t b1) {
    asm volatile(
        "mma.sync.aligned.m16n8k8.row.col.f32.tf32.tf32.f32 "
        "{%0,%1,%2,%3}, {%4,%5,%6,%7}, {%8,%9}, {%0,%1,%2,%3};"
        : "+f"(c[0]), "+f"(c[1]), "+f"(c[2]), "+f"(c[3])
        : "r"(a0), "r"(a1), "r"(a2), "r"(a3), "r"(b0), "r"(b1));
}

// =====================================================================
// TF32 TN GEMM tile: C[128,128] = A[128,K] * W[128,K]^T (+bias)
// 256 threads = 8 warps in 2(m)x4(n); warp tile 64x32; BK=16.
// smem rows padded to 20 u32 -> conflict-free fragment loads.
// =====================================================================
#define BKP 20

__device__ __forceinline__ void gemm_tn_tile_mma(
    const float* __restrict__ A, int lda,      // (m0, 0)
    const float* __restrict__ W,               // (n0, 0), ld = K
    const float* __restrict__ bias,            // n0 or null
    float* __restrict__ C, int ldc,            // (m0, n0)
    int K)
{
    __shared__ __align__(16) uint32_t As[128 * BKP];
    __shared__ __align__(16) uint32_t Bs[128 * BKP];

    const int tid  = threadIdx.x;
    const int warp = tid >> 5, lane = tid & 31;
    const int wm = warp >> 2, wn = warp & 3;     // 2 x 4 warp grid
    const int g = lane >> 2, t = lane & 3;

    // loader: 512 float4 per tile per operand; each thread handles ids tid, tid+256
    const int r0 = tid >> 2,          ck0 = (tid & 3) * 4;
    const int r1 = (tid + 256) >> 2,  ck1 = ((tid + 256) & 3) * 4;

    const float* Ap0 = A + (size_t)r0 * lda + ck0;
    const float* Ap1 = A + (size_t)r1 * lda + ck1;
    const float* Wp0 = W + (size_t)r0 * K + ck0;
    const float* Wp1 = W + (size_t)r1 * K + ck1;

    float acc[4][4][4];
#pragma unroll
    for (int i = 0; i < 4; i++)
#pragma unroll
        for (int j = 0; j < 4; j++)
#pragma unroll
            for (int c = 0; c < 4; c++) acc[i][j][c] = 0.f;

    float4 av0 = *(const float4*)Ap0;
    float4 av1 = *(const float4*)Ap1;
    float4 bv0 = *(const float4*)Wp0;
    float4 bv1 = *(const float4*)Wp1;

    for (int k0 = 0; k0 < K; k0 += 16) {
        __syncthreads();
        {
            uint4 u;
            u.x = f2tf32(av0.x); u.y = f2tf32(av0.y); u.z = f2tf32(av0.z); u.w = f2tf32(av0.w);
            *(uint4*)&As[r0 * BKP + ck0] = u;
            u.x = f2tf32(av1.x); u.y = f2tf32(av1.y); u.z = f2tf32(av1.z); u.w = f2tf32(av1.w);
            *(uint4*)&As[r1 * BKP + ck1] = u;
            u.x = f2tf32(bv0.x); u.y = f2tf32(bv0.y); u.z = f2tf32(bv0.z); u.w = f2tf32(bv0.w);
            *(uint4*)&Bs[r0 * BKP + ck0] = u;
            u.x = f2tf32(bv1.x); u.y = f2tf32(bv1.y); u.z = f2tf32(bv1.z); u.w = f2tf32(bv1.w);
            *(uint4*)&Bs[r1 * BKP + ck1] = u;
        }
        __syncthreads();
        if (k0 + 16 < K) {                 // prefetch next K-slab
            av0 = *(const float4*)(Ap0 + k0 + 16);
            av1 = *(const float4*)(Ap1 + k0 + 16);
            bv0 = *(const float4*)(Wp0 + k0 + 16);
            bv1 = *(const float4*)(Wp1 + k0 + 16);
        }
#pragma unroll
        for (int kk = 0; kk < 16; kk += 8) {
            uint32_t af[4][4], bf[4][2];
#pragma unroll
            for (int mi = 0; mi < 4; mi++) {
                int row = wm * 64 + mi * 16 + g;
                af[mi][0] = As[row * BKP + kk + t];
                af[mi][1] = As[(row + 8) * BKP + kk + t];
                af[mi][2] = As[row * BKP + kk + t + 4];
                af[mi][3] = As[(row + 8) * BKP + kk + t + 4];
            }
#pragma unroll
            for (int nj = 0; nj < 4; nj++) {
                int rowb = wn * 32 + nj * 8 + g;
                bf[nj][0] = Bs[rowb * BKP + kk + t];
                bf[nj][1] = Bs[rowb * BKP + kk + t + 4];
            }
#pragma unroll
            for (int mi = 0; mi < 4; mi++)
#pragma unroll
                for (int nj = 0; nj < 4; nj++)
                    mma_tf32(acc[mi][nj], af[mi][0], af[mi][1], af[mi][2], af[mi][3],
                             bf[nj][0], bf[nj][1]);
        }
    }

    // epilogue: C layout c0=(g,2t) c1=(g,2t+1) c2=(g+8,2t) c3=(g+8,2t+1)
#pragma unroll
    for (int mi = 0; mi < 4; mi++) {
        int row = wm * 64 + mi * 16 + g;
#pragma unroll
        for (int nj = 0; nj < 4; nj++) {
            int col = wn * 32 + nj * 8 + 2 * t;
            float b0 = bias ? bias[col] : 0.f;
            float b1 = bias ? bias[col + 1] : 0.f;
            *(float2*)(C + (size_t)row * ldc + col) =
                make_float2(acc[mi][nj][0] + b0, acc[mi][nj][1] + b1);
            *(float2*)(C + (size_t)(row + 8) * ldc + col) =
                make_float2(acc[mi][nj][2] + b0, acc[mi][nj][3] + b1);
        }
    }
}

// Fused QKV projection: grid (32, 36). by<28 -> Q, <32 -> K, else V.
__global__ __launch_bounds__(256) void qkv_kernel(
    const float* __restrict__ x,
    const float* __restrict__ wq, const float* __restrict__ bq,
    const float* __restrict__ wk, const float* __restrict__ bk,
    const float* __restrict__ wv, const float* __restrict__ bv)
{
    int m0 = blockIdx.x * 128;
    int by = blockIdx.y;
    const float* W; const float* bias; float* C; int ldc;
    if (by < 28) {
        W = wq + (size_t)by * 128 * DD;  bias = bq + by * 128;
        C = g_q + (size_t)m0 * DD + by * 128; ldc = DD;
    } else if (by < 32) {
        int nb = by - 28;
        W = wk + (size_t)nb * 128 * DD;  bias = bk + nb * 128;
        C = g_k + (size_t)m0 * 512 + nb * 128; ldc = 512;
    } else {
        int nb = by - 32;
        W = wv + (size_t)nb * 128 * DD;  bias = bv + nb * 128;
        C = g_v + (size_t)m0 * 512 + nb * 128; ldc = 512;
    }
    gemm_tn_tile_mma(x + (size_t)m0 * DD, DD, W, bias, C, ldc, DD);
}

// Output projection: grid (32, 28).
__global__ __launch_bounds__(256) void oproj_kernel(
    const float* __restrict__ wo, float* __restrict__ out)
{
    int m0 = blockIdx.x * 128;
    int n0 = blockIdx.y * 128;
    gemm_tn_tile_mma(g_o + (size_t)m0 * DD, DD, wo + (size_t)n0 * DD, nullptr,
                     out + (size_t)m0 * DD + n0, DD, DD);
}

// =====================================================================
// RoPE on g_q and g_k (in place).
// =====================================================================
__global__ __launch_bounds__(256) void rope_kernel(
    const float* __restrict__ cosT, const float* __restrict__ sinT,
    const int* __restrict__ spp)
{
    const int QP = MM * HH * 64;
    const int KP = MM * KVH * 64;
    int idx = blockIdx.x * blockDim.x + threadIdx.x;
    if (idx >= QP + KP) return;
    int sp = spp[0];
    float* buf; int nh; int i2;
    if (idx < QP) { buf = g_q; nh = HH;  i2 = idx; }
    else          { buf = g_k; nh = KVH; i2 = idx - QP; }
    int d2 = i2 & 63;
    int t  = i2 >> 6;
    int h  = t % nh;
    int m  = t / nh;
    int s  = m & (SS - 1);
    int pos = sp + s;
    float c  = cosT[pos * 64 + d2];
    float sn = sinT[pos * 64 + d2];
    size_t off = (size_t)m * (nh * HDIM) + h * HDIM + 2 * d2;
    float2 v = *(float2*)(buf + off);
    float yr = v.x * c - v.y * sn;
    float yi = v.x * sn + v.y * c;
    *(float2*)(buf + off) = make_float2(yr, yi);
}

// =====================================================================
// Flash attention (causal), fp32. BM=BN=64, HD=128, 256 threads (16x16),
// 4x4 S-microtile, online softmax. Dynamic smem ~117 KB.
// =====================================================================
#define ATTN_SMEM_FLOATS (2*128*68 + 64*128 + 64*68)

__global__ __launch_bounds__(256) void attn_kernel()
{
    extern __shared__ float sm[];
    float* Qt = sm;                        // [128][68]
    float* Kt = sm + 128*68;               // [128][68]
    float* Vs = sm + 2*128*68;             // [64][128]
    float* Ps = sm + 2*128*68 + 64*128;    // [64][68]

    const int qt = gridDim.x - 1 - blockIdx.x;
    const int h  = blockIdx.y;
    const int b  = blockIdx.z;
    const int kvh = h / NREP;
    const int tid = threadIdx.x;
    const int ty = tid >> 4, tx = tid & 15;

    const int qrow0 = b * SS + qt * 64;

    {
        const float* qbase = g_q + (size_t)qrow0 * DD + h * HDIM;
#pragma unroll
        for (int t = 0; t < 8; t++) {
            int f4 = tid + t * 256;
            int row = f4 >> 5, d4 = f4 & 31;
            float4 qv = *(const float4*)(qbase + (size_t)row * DD + d4 * 4);
            Qt[(d4*4+0)*68 + row] = qv.x;
            Qt[(d4*4+1)*68 + row] = qv.y;
            Qt[(d4*4+2)*68 + row] = qv.z;
            Qt[(d4*4+3)*68 + row] = qv.w;
        }
    }

    float m_i[4], l_i[4], o_acc[4][8];
#pragma unroll
    for (int i = 0; i < 4; i++) {
        m_i[i] = -1e30f; l_i[i] = 0.f;
#pragma unroll
        for (int c = 0; c < 8; c++) o_acc[i][c] = 0.f;
    }

    for (int nt = 0; nt <= qt; nt++) {
        const int n0 = nt * 64;
        const float* kbase = g_k + (size_t)(b * SS + n0) * 512 + kvh * HDIM;
        const float* vbase = g_v + (size_t)(b * SS + n0) * 512 + kvh * HDIM;

        __syncthreads();
#pragma unroll
        for (int t = 0; t < 8; t++) {
            int f4 = tid + t * 256;
            int row = f4 >> 5, d4 = f4 & 31;
            float4 kv4 = *(const float4*)(kbase + (size_t)row * 512 + d4 * 4);
            Kt[(d4*4+0)*68 + row] = kv4.x;
            Kt[(d4*4+1)*68 + row] = kv4.y;
            Kt[(d4*4+2)*68 + row] = kv4.z;
            Kt[(d4*4+3)*68 + row] = kv4.w;
            float4 vv4 = *(const float4*)(vbase + (size_t)row * 512 + d4 * 4);
            *(float4*)&Vs[row * 128 + d4 * 4] = vv4;
        }
        __syncthreads();

        float s[4][4];
#pragma unroll
        for (int i = 0; i < 4; i++)
#pragma unroll
            for (int j = 0; j < 4; j++) s[i][j] = 0.f;

#pragma unroll 4
        for (int d = 0; d < 128; d++) {
            float4 q4 = *(const float4*)&Qt[d*68 + ty*4];
            float4 k4 = *(const float4*)&Kt[d*68 + tx*4];
            float qa[4] = {q4.x, q4.y, q4.z, q4.w};
            float ka[4] = {k4.x, k4.y, k4.z, k4.w};
#pragma unroll
            for (int i = 0; i < 4; i++)
#pragma unroll
                for (int j = 0; j < 4; j++)
                    s[i][j] = fmaf(qa[i], ka[j], s[i][j]);
        }

        const bool diag = (nt == qt);

#pragma unroll
        for (int i = 0; i < 4; i++) {
#pragma unroll
            for (int j = 0; j < 4; j++) {
                float val = s[i][j] * QK_SCALE;
                if (diag && (tx*4 + j > ty*4 + i)) val = -1e30f;
                s[i][j] = val;
            }
            float mt = fmaxf(fmaxf(s[i][0], s[i][1]), fmaxf(s[i][2], s[i][3]));
#pragma unroll
            for (int off = 8; off > 0; off >>= 1)
                mt = fmaxf(mt, __shfl_xor_sync(0xffffffffu, mt, off));
            float mnew  = fmaxf(m_i[i], mt);
            float alpha = __expf(m_i[i] - mnew);
            m_i[i] = mnew;
            float p0 = __expf(s[i][0] - mnew);
            float p1 = __expf(s[i][1] - mnew);
            float p2 = __expf(s[i][2] - mnew);
            float p3 = __expf(s[i][3] - mnew);
            float rs = (p0 + p1) + (p2 + p3);
#pragma unroll
            for (int off = 8; off > 0; off >>= 1)
                rs += __shfl_xor_sync(0xffffffffu, rs, off);
            l_i[i] = l_i[i] * alpha + rs;
#pragma unroll
            for (int c = 0; c < 8; c++) o_acc[i][c] *= alpha;
            int pr = (ty*4 + i) * 68 + tx*4;
            Ps[pr + 0] = p0; Ps[pr + 1] = p1; Ps[pr + 2] = p2; Ps[pr + 3] = p3;
        }
        __syncthreads();

#pragma unroll 2
        for (int kc = 0; kc < 64; kc++) {
            float4 va = *(const float4*)&Vs[kc*128 + tx*4];
            float4 vb = *(const float4*)&Vs[kc*128 + 64 + tx*4];
#pragma unroll
            for (int i = 0; i < 4; i++) {
                float pp = Ps[(ty*4+i)*68 + kc];
                o_acc[i][0] = fmaf(pp, va.x, o_acc[i][0]);
                o_acc[i][1] = fmaf(pp, va.y, o_acc[i][1]);
                o_acc[i][2] = fmaf(pp, va.z, o_acc[i][2]);
                o_acc[i][3] = fmaf(pp, va.w, o_acc[i][3]);
                o_acc[i][4] = fmaf(pp, vb.x, o_acc[i][4]);
                o_acc[i][5] = fmaf(pp, vb.y, o_acc[i][5]);
                o_acc[i][6] = fmaf(pp, vb.z, o_acc[i][6]);
                o_acc[i][7] = fmaf(pp, vb.w, o_acc[i][7]);
            }
        }
    }

    float* obase = g_o + (size_t)qrow0 * DD + h * HDIM;
#pragma unroll
    for (int i = 0; i < 4; i++) {
        int r = ty*4 + i;
        float inv = 1.0f / l_i[i];
        float4 r0 = make_float4(o_acc[i][0]*inv, o_acc[i][1]*inv,
                                o_acc[i][2]*inv, o_acc[i][3]*inv);
        float4 r1 = make_float4(o_acc[i][4]*inv, o_acc[i][5]*inv,
                                o_acc[i][6]*inv, o_acc[i][7]*inv);
        *(float4*)(obase + (size_t)r * DD + tx*4)      = r0;
        *(float4*)(obase + (size_t)r * DD + 64 + tx*4) = r1;
    }
}

// =====================================================================
// launch
// =====================================================================
extern "C" void kernel_launch(void* const* d_in, const int* in_sizes, int n_in,
                              void* d_out, int out_size)
{
    const float* x    = (const float*)d_in[0];
    const float* wq_w = (const float*)d_in[1];
    const float* wq_b = (const float*)d_in[2];
    const float* wk_w = (const float*)d_in[3];
    const float* wk_b = (const float*)d_in[4];
    const float* wv_w = (const float*)d_in[5];
    const float* wv_b = (const float*)d_in[6];
    const float* wo_w = (const float*)d_in[7];
    const float* fcos = (const float*)d_in[10];
    const float* fsin = (const float*)d_in[11];
    const int*   spos = (const int*)d_in[13];
    float* out = (float*)d_out;

    size_t attn_smem = (size_t)ATTN_SMEM_FLOATS * sizeof(float);
    cudaFuncSetAttribute(attn_kernel,
                         cudaFuncAttributeMaxDynamicSharedMemorySize,
                         (int)attn_smem);

    qkv_kernel<<<dim3(32, 36), 256>>>(x, wq_w, wq_b, wk_w, wk_b, wv_w, wv_b);

    int pairs = MM * HH * 64 + MM * KVH * 64;
    rope_kernel<<<(pairs + 255) / 256, 256>>>(fcos, fsin, spos);

    attn_kernel<<<dim3(32, 28, 2), 256, attn_smem>>>();

    oproj_kernel<<<dim3(32, 28), 256>>>(wo_w, out);
}

// round 3
// speedup vs baseline: 1.7685x; 1.1408x over previous
#include <cuda_runtime.h>
#include <cstdint>

// ---------------- problem constants ----------------
#define BB 2
#define SS 2048
#define DD 3584
#define HH 28
#define KVH 4
#define HDIM 128
#define NREP 7
#define MM (BB*SS)            // 4096
#define QK_SCALE 0.08838834764831845f
#define GEMM_K DD
#define KITERS (GEMM_K/16)    // 224

// ---------------- scratch ----------------
__device__ float g_q[(size_t)MM * DD];
__device__ float g_k[(size_t)MM * 512];
__device__ float g_v[(size_t)MM * 512];
__device__ float g_o[(size_t)MM * DD];

// ---------------- helpers ----------------
__device__ __forceinline__ uint32_t f2tf32(float f) {
    uint32_t u;
    asm("cvt.rna.tf32.f32 %0, %1;" : "=r"(u) : "f"(f));
    return u;
}
__device__ __forceinline__ void mma_tf32(float c[4],
                                         uint32_t a0, uint32_t a1, uint32_t a2, uint32_t a3,
                                         uint32_t b0, uint32_t b1) {
    asm volatile(
        "mma.sync.aligned.m16n8k8.row.col.f32.tf32.tf32.f32 "
        "{%0,%1,%2,%3}, {%4,%5,%6,%7}, {%8,%9}, {%0,%1,%2,%3};"
        : "+f"(c[0]), "+f"(c[1]), "+f"(c[2]), "+f"(c[3])
        : "r"(a0), "r"(a1), "r"(a2), "r"(a3), "r"(b0), "r"(b1));
}
__device__ __forceinline__ void cp16(uint32_t s, const float* g) {
    asm volatile("cp.async.cg.shared.global [%0], [%1], 16;" :: "r"(s), "l"(g));
}

// =====================================================================
// TF32 TN GEMM: C[128,256] = A[128,K] * W[256,K]^T (+bias)
// 256 thr = 8 warps (2m x 4n), warp tile 64x64, BK=16, 3-stage cp.async.
// smem rows padded to 20 words -> conflict-free fragment loads.
// =====================================================================
#define BKP 20
#define A_WORDS (128*BKP)                 // 2560
#define B_WORDS (256*BKP)                 // 5120
#define STG_WORDS (A_WORDS + B_WORDS)     // 7680
#define NSTG 3
#define GEMM_SMEM_BYTES (NSTG*STG_WORDS*4)  // 92160

__device__ __forceinline__ void gemm_tile(
    const float* __restrict__ A, int lda,
    const float* __restrict__ W,
    const float* __restrict__ bias,
    float* __restrict__ C, int ldc)
{
    extern __shared__ float smf[];
    uint32_t sbase = (uint32_t)__cvta_generic_to_shared(smf);

    const int tid  = threadIdx.x;
    const int warp = tid >> 5, lane = tid & 31;
    const int wm = warp >> 2, wn = warp & 3;
    const int g = lane >> 2, t = lane & 3;

    const int arow = tid >> 2, akc = (tid & 3) * 4;
    const float* Ag = A + (size_t)arow * lda + akc;
    const float* Wg = W + (size_t)arow * GEMM_K + akc;
    const uint32_t soff = (uint32_t)(arow * BKP + akc) * 4;

    auto issue = [&](int stage, int it) {
        uint32_t sa = sbase + (uint32_t)stage * (STG_WORDS * 4) + soff;
        const float* ag = Ag + it * 16;
        cp16(sa,                ag);
        cp16(sa + 64*BKP*4,     ag + (size_t)64 * lda);
        uint32_t sb = sa + A_WORDS * 4;
        const float* wg = Wg + it * 16;
        cp16(sb,                wg);
        cp16(sb + 64*BKP*4,     wg + (size_t)64  * GEMM_K);
        cp16(sb + 128*BKP*4,    wg + (size_t)128 * GEMM_K);
        cp16(sb + 192*BKP*4,    wg + (size_t)192 * GEMM_K);
        asm volatile("cp.async.commit_group;");
    };

    float acc[4][8][4];
#pragma unroll
    for (int mi = 0; mi < 4; mi++)
#pragma unroll
        for (int nj = 0; nj < 8; nj++)
#pragma unroll
            for (int c = 0; c < 4; c++) acc[mi][nj][c] = 0.f;

    issue(0, 0);
    issue(1, 1);

    int stage = 0;
    for (int it = 0; it < KITERS; it++) {
        if (it + 2 < KITERS) {
            asm volatile("cp.async.wait_group 1;");
        } else {
            asm volatile("cp.async.wait_group 0;");
        }
        __syncthreads();
        if (it + 2 < KITERS) {
            int ns = stage + 2; if (ns >= NSTG) ns -= NSTG;
            issue(ns, it + 2);
        }
        const float* ab = smf + stage * STG_WORDS;
        const float* bb = ab + A_WORDS;
#pragma unroll
        for (int kk = 0; kk < 16; kk += 8) {
            uint32_t af[4][4], bf[8][2];
#pragma unroll
            for (int mi = 0; mi < 4; mi++) {
                int row = wm * 64 + mi * 16 + g;
                af[mi][0] = f2tf32(ab[row * BKP + kk + t]);
                af[mi][1] = f2tf32(ab[(row + 8) * BKP + kk + t]);
                af[mi][2] = f2tf32(ab[row * BKP + kk + t + 4]);
                af[mi][3] = f2tf32(ab[(row + 8) * BKP + kk + t + 4]);
            }
#pragma unroll
            for (int nj = 0; nj < 8; nj++) {
                int rowb = wn * 64 + nj * 8 + g;
                bf[nj][0] = f2tf32(bb[rowb * BKP + kk + t]);
                bf[nj][1] = f2tf32(bb[rowb * BKP + kk + t + 4]);
            }
#pragma unroll
            for (int mi = 0; mi < 4; mi++)
#pragma unroll
                for (int nj = 0; nj < 8; nj++)
                    mma_tf32(acc[mi][nj], af[mi][0], af[mi][1], af[mi][2], af[mi][3],
                             bf[nj][0], bf[nj][1]);
        }
        stage++; if (stage >= NSTG) stage = 0;
    }

#pragma unroll
    for (int mi = 0; mi < 4; mi++) {
        int row = wm * 64 + mi * 16 + g;
#pragma unroll
        for (int nj = 0; nj < 8; nj++) {
            int col = wn * 64 + nj * 8 + 2 * t;
            float b0 = bias ? bias[col] : 0.f;
            float b1 = bias ? bias[col + 1] : 0.f;
            *(float2*)(C + (size_t)row * ldc + col) =
                make_float2(acc[mi][nj][0] + b0, acc[mi][nj][1] + b1);
            *(float2*)(C + (size_t)(row + 8) * ldc + col) =
                make_float2(acc[mi][nj][2] + b0, acc[mi][nj][3] + b1);
        }
    }
}

// Fused QKV projection: grid (32, 18). by<14 -> Q, 14..15 -> K, else V.
__global__ __launch_bounds__(256) void qkv_kernel(
    const float* __restrict__ x,
    const float* __restrict__ wq, const float* __restrict__ bq,
    const float* __restrict__ wk, const float* __restrict__ bk,
    const float* __restrict__ wv, const float* __restrict__ bv)
{
    int m0 = blockIdx.x * 128;
    int by = blockIdx.y;
    const float* W; const float* bias; float* C; int ldc;
    if (by < 14) {
        W = wq + (size_t)by * 256 * DD;  bias = bq + by * 256;
        C = g_q + (size_t)m0 * DD + by * 256; ldc = DD;
    } else if (by < 16) {
        int nb = by - 14;
        W = wk + (size_t)nb * 256 * DD;  bias = bk + nb * 256;
        C = g_k + (size_t)m0 * 512 + nb * 256; ldc = 512;
    } else {
        int nb = by - 16;
        W = wv + (size_t)nb * 256 * DD;  bias = bv + nb * 256;
        C = g_v + (size_t)m0 * 512 + nb * 256; ldc = 512;
    }
    gemm_tile(x + (size_t)m0 * DD, DD, W, bias, C, ldc);
}

// Output projection: grid (32, 14).
__global__ __launch_bounds__(256) void oproj_kernel(
    const float* __restrict__ wo, float* __restrict__ out)
{
    int m0 = blockIdx.x * 128;
    int n0 = blockIdx.y * 256;
    gemm_tile(g_o + (size_t)m0 * DD, DD, wo + (size_t)n0 * DD, nullptr,
              out + (size_t)m0 * DD + n0, DD);
}

// =====================================================================
// RoPE on g_q and g_k (in place).
// =====================================================================
__global__ __launch_bounds__(256) void rope_kernel(
    const float* __restrict__ cosT, const float* __restrict__ sinT,
    const int* __restrict__ spp)
{
    const int QP = MM * HH * 64;
    const int KP = MM * KVH * 64;
    int idx = blockIdx.x * blockDim.x + threadIdx.x;
    if (idx >= QP + KP) return;
    int sp = spp[0];
    float* buf; int nh; int i2;
    if (idx < QP) { buf = g_q; nh = HH;  i2 = idx; }
    else          { buf = g_k; nh = KVH; i2 = idx - QP; }
    int d2 = i2 & 63;
    int t  = i2 >> 6;
    int h  = t % nh;
    int m  = t / nh;
    int s  = m & (SS - 1);
    int pos = sp + s;
    float c  = cosT[pos * 64 + d2];
    float sn = sinT[pos * 64 + d2];
    size_t off = (size_t)m * (nh * HDIM) + h * HDIM + 2 * d2;
    float2 v = *(float2*)(buf + off);
    float yr = v.x * c - v.y * sn;
    float yi = v.x * sn + v.y * c;
    *(float2*)(buf + off) = make_float2(yr, yi);
}

// =====================================================================
// Flash attention (causal), fp32. BM=128, BN=64, HD=128, 256 thr (16x16),
// 8x4 S-microtile, 8x8 O-microtile, online softmax. smem ~166 KB.
// grid: (16 q-tiles [reversed], 28 heads, 2 batches)
// =====================================================================
#define QTP 132
#define KTP 68
#define ATTN_SMEM_WORDS (128*QTP + 128*KTP + 64*128 + 128*KTP)
#define ATTN_SMEM_BYTES (ATTN_SMEM_WORDS*4)   // 169984

__global__ __launch_bounds__(256) void attn_kernel()
{
    extern __shared__ float sm[];
    float* Qt = sm;                       // [128 d][132 rows]
    float* Kt = Qt + 128*QTP;             // [128 d][68 rows]
    float* Vs = Kt + 128*KTP;             // [64 rows][128 d]
    float* Ps = Vs + 64*128;              // [128 rows][68 cols]

    const int qt = gridDim.x - 1 - blockIdx.x;    // 0..15 heavy-first
    const int h  = blockIdx.y;
    const int b  = blockIdx.z;
    const int kvh = h / NREP;
    const int tid = threadIdx.x;
    const int ty = tid >> 4, tx = tid & 15;

    const int qrow0 = b * SS + qt * 128;

    // ---- load Q tile (128x128) transposed into Qt ----
    {
        const float* qbase = g_q + (size_t)qrow0 * DD + h * HDIM;
#pragma unroll
        for (int tt = 0; tt < 16; tt++) {
            int f4 = tid + tt * 256;
            int row = f4 >> 5, d4 = f4 & 31;
            float4 qv = *(const float4*)(qbase + (size_t)row * DD + d4 * 4);
            Qt[(d4*4+0)*QTP + row] = qv.x;
            Qt[(d4*4+1)*QTP + row] = qv.y;
            Qt[(d4*4+2)*QTP + row] = qv.z;
            Qt[(d4*4+3)*QTP + row] = qv.w;
        }
    }

    float m_i[8], l_i[8], o_acc[8][8];
#pragma unroll
    for (int i = 0; i < 8; i++) {
        m_i[i] = -1e30f; l_i[i] = 0.f;
#pragma unroll
        for (int c = 0; c < 8; c++) o_acc[i][c] = 0.f;
    }

    const int ntmax = 2 * qt + 1;
    for (int nt = 0; nt <= ntmax; nt++) {
        const float* kb = g_k + (size_t)(b * SS + nt * 64) * 512 + kvh * HDIM;
        const float* vb = g_v + (size_t)(b * SS + nt * 64) * 512 + kvh * HDIM;

        __syncthreads();   // prior iter done reading Kt/Vs (also fences Q fill)
#pragma unroll
        for (int tt = 0; tt < 8; tt++) {
            int f4 = tid + tt * 256;
            int row = f4 >> 5, d4 = f4 & 31;
            float4 k4 = *(const float4*)(kb + (size_t)row * 512 + d4 * 4);
            Kt[(d4*4+0)*KTP + row] = k4.x;
            Kt[(d4*4+1)*KTP + row] = k4.y;
            Kt[(d4*4+2)*KTP + row] = k4.z;
            Kt[(d4*4+3)*KTP + row] = k4.w;
            *(float4*)&Vs[row * 128 + d4 * 4] =
                *(const float4*)(vb + (size_t)row * 512 + d4 * 4);
        }
        __syncthreads();

        // ---- S = Q K^T : 128x64x128, 8x4 per thread ----
        float s[8][4];
#pragma unroll
        for (int i = 0; i < 8; i++)
#pragma unroll
            for (int j = 0; j < 4; j++) s[i][j] = 0.f;

#pragma unroll 4
        for (int d = 0; d < 128; d++) {
            float4 q0 = *(const float4*)&Qt[d*QTP + ty*8];
            float4 q1 = *(const float4*)&Qt[d*QTP + ty*8 + 4];
            float4 kv = *(const float4*)&Kt[d*KTP + tx*4];
            float qa[8] = {q0.x,q0.y,q0.z,q0.w, q1.x,q1.y,q1.z,q1.w};
            float ka[4] = {kv.x,kv.y,kv.z,kv.w};
#pragma unroll
            for (int i = 0; i < 8; i++)
#pragma unroll
                for (int j = 0; j < 4; j++)
                    s[i][j] = fmaf(qa[i], ka[j], s[i][j]);
        }

        const bool edge = (nt >= 2 * qt);
        const int colbase = (nt - 2 * qt) * 64 + tx * 4;  // only used if edge

        // ---- online softmax ----
#pragma unroll
        for (int i = 0; i < 8; i++) {
            int lrow = ty * 8 + i;
#pragma unroll
            for (int j = 0; j < 4; j++) {
                float val = s[i][j] * QK_SCALE;
                if (edge && (colbase + j > lrow)) val = -1e30f;
                s[i][j] = val;
            }
            float mt = fmaxf(fmaxf(s[i][0], s[i][1]), fmaxf(s[i][2], s[i][3]));
#pragma unroll
            for (int off = 8; off > 0; off >>= 1)
                mt = fmaxf(mt, __shfl_xor_sync(0xffffffffu, mt, off));
            float mnew  = fmaxf(m_i[i], mt);
            float alpha = __expf(m_i[i] - mnew);
            m_i[i] = mnew;
            float p0 = __expf(s[i][0] - mnew);
            float p1 = __expf(s[i][1] - mnew);
            float p2 = __expf(s[i][2] - mnew);
            float p3 = __expf(s[i][3] - mnew);
            float rs = (p0 + p1) + (p2 + p3);
#pragma unroll
            for (int off = 8; off > 0; off >>= 1)
                rs += __shfl_xor_sync(0xffffffffu, rs, off);
            l_i[i] = l_i[i] * alpha + rs;
#pragma unroll
            for (int c = 0; c < 8; c++) o_acc[i][c] *= alpha;
            int pr = lrow * KTP + tx * 4;
            Ps[pr+0] = p0; Ps[pr+1] = p1; Ps[pr+2] = p2; Ps[pr+3] = p3;
        }
        __syncthreads();

        // ---- O += P V : 128x128x64, 8x8 per thread ----
#pragma unroll 2
        for (int kc = 0; kc < 64; kc++) {
            float4 va = *(const float4*)&Vs[kc*128 + tx*4];
            float4 vb4 = *(const float4*)&Vs[kc*128 + 64 + tx*4];
#pragma unroll
            for (int i = 0; i < 8; i++) {
                float pp = Ps[(ty*8+i)*KTP + kc];
                o_acc[i][0] = fmaf(pp, va.x,  o_acc[i][0]);
                o_acc[i][1] = fmaf(pp, va.y,  o_acc[i][1]);
                o_acc[i][2] = fmaf(pp, va.z,  o_acc[i][2]);
                o_acc[i][3] = fmaf(pp, va.w,  o_acc[i][3]);
                o_acc[i][4] = fmaf(pp, vb4.x, o_acc[i][4]);
                o_acc[i][5] = fmaf(pp, vb4.y, o_acc[i][5]);
                o_acc[i][6] = fmaf(pp, vb4.z, o_acc[i][6]);
                o_acc[i][7] = fmaf(pp, vb4.w, o_acc[i][7]);
            }
        }
    }

    // ---- epilogue ----
    float* obase = g_o + (size_t)qrow0 * DD + h * HDIM;
#pragma unroll
    for (int i = 0; i < 8; i++) {
        int r = ty * 8 + i;
        float inv = 1.0f / l_i[i];
        float4 r0 = make_float4(o_acc[i][0]*inv, o_acc[i][1]*inv,
                                o_acc[i][2]*inv, o_acc[i][3]*inv);
        float4 r1 = make_float4(o_acc[i][4]*inv, o_acc[i][5]*inv,
                                o_acc[i][6]*inv, o_acc[i][7]*inv);
        *(float4*)(obase + (size_t)r * DD + tx*4)      = r0;
        *(float4*)(obase + (size_t)r * DD + 64 + tx*4) = r1;
    }
}

// =====================================================================
// launch
// =====================================================================
extern "C" void kernel_launch(void* const* d_in, const int* in_sizes, int n_in,
                              void* d_out, int out_size)
{
    const float* x    = (const float*)d_in[0];
    const float* wq_w = (const float*)d_in[1];
    const float* wq_b = (const float*)d_in[2];
    const float* wk_w = (const float*)d_in[3];
    const float* wk_b = (const float*)d_in[4];
    const float* wv_w = (const float*)d_in[5];
    const float* wv_b = (const float*)d_in[6];
    const float* wo_w = (const float*)d_in[7];
    const float* fcos = (const float*)d_in[10];
    const float* fsin = (const float*)d_in[11];
    const int*   spos = (const int*)d_in[13];
    float* out = (float*)d_out;

    cudaFuncSetAttribute(qkv_kernel,
                         cudaFuncAttributeMaxDynamicSharedMemorySize, GEMM_SMEM_BYTES);
    cudaFuncSetAttribute(oproj_kernel,
                         cudaFuncAttributeMaxDynamicSharedMemorySize, GEMM_SMEM_BYTES);
    cudaFuncSetAttribute(attn_kernel,
                         cudaFuncAttributeMaxDynamicSharedMemorySize, ATTN_SMEM_BYTES);

    qkv_kernel<<<dim3(32, 18), 256, GEMM_SMEM_BYTES>>>(
        x, wq_w, wq_b, wk_w, wk_b, wv_w, wv_b);

    int pairs = MM * HH * 64 + MM * KVH * 64;
    rope_kernel<<<(pairs + 255) / 256, 256>>>(fcos, fsin, spos);

    attn_kernel<<<dim3(16, 28, 2), 256, ATTN_SMEM_BYTES>>>();

    oproj_kernel<<<dim3(32, 14), 256, GEMM_SMEM_BYTES>>>(wo_w, out);
}

// round 4
// speedup vs baseline: 1.8374x; 1.0390x over previous
#include <cuda_runtime.h>
#include <cstdint>

// ---------------- problem constants ----------------
#define BB 2
#define SS 2048
#define DD 3584
#define HH 28
#define KVH 4
#define HDIM 128
#define NREP 7
#define MM (BB*SS)            // 4096
#define QK_SCALE 0.08838834764831845f
#define GEMM_K DD
#define KITERS (GEMM_K/16)    // 224

// ---------------- scratch ----------------
__device__ float g_q[(size_t)MM * DD];
__device__ float g_k[(size_t)MM * 512];
__device__ float g_v[(size_t)MM * 512];
__device__ float g_o[(size_t)MM * DD];

// ---------------- helpers ----------------
__device__ __forceinline__ uint32_t f2tf32(float f) {
    uint32_t u;
    asm("cvt.rna.tf32.f32 %0, %1;" : "=r"(u) : "f"(f));
    return u;
}
__device__ __forceinline__ void mma_tf32(float c[4],
                                         uint32_t a0, uint32_t a1, uint32_t a2, uint32_t a3,
                                         uint32_t b0, uint32_t b1) {
    asm volatile(
        "mma.sync.aligned.m16n8k8.row.col.f32.tf32.tf32.f32 "
        "{%0,%1,%2,%3}, {%4,%5,%6,%7}, {%8,%9}, {%0,%1,%2,%3};"
        : "+f"(c[0]), "+f"(c[1]), "+f"(c[2]), "+f"(c[3])
        : "r"(a0), "r"(a1), "r"(a2), "r"(a3), "r"(b0), "r"(b1));
}
__device__ __forceinline__ void cp16(uint32_t s, const float* g) {
    asm volatile("cp.async.cg.shared.global [%0], [%1], 16;" :: "r"(s), "l"(g));
}

// =====================================================================
// TF32 TN GEMM: C[128,128] = A[128,K] * W[128,K]^T (+bias),  K=3584.
// 128 thr = 4 warps (2m x 2n), warp tile 64x64, BK=16, 3-stage cp.async.
// smem rows padded to 20 words -> conflict-free fragment LDS.
// 2 CTAs / SM (reg-capped via launch_bounds) -> overlapped pipelines.
// =====================================================================
#define BKP 20
#define A_WORDS (128*BKP)                  // 2560
#define STG_WORDS (2*A_WORDS)              // 5120 (A + B)
#define NSTG 3
#define GEMM_SMEM_BYTES (NSTG*STG_WORDS*4) // 61440

__device__ __forceinline__ void gemm_tile(
    const float* __restrict__ A,           // (m0, 0), ld = DD
    const float* __restrict__ W,           // (n0, 0), ld = DD
    const float* __restrict__ bias,        // n0 or null
    float* __restrict__ C, int ldc)
{
    extern __shared__ float smf[];
    uint32_t sbase = (uint32_t)__cvta_generic_to_shared(smf);

    const int tid  = threadIdx.x;
    const int warp = tid >> 5, lane = tid & 31;
    const int wm = warp >> 1, wn = warp & 1;       // 2 x 2 warp grid
    const int g = lane >> 2, t = lane & 3;

    const int r  = tid >> 2;                       // 0..31
    const int kc = (tid & 3) * 4;
    const float* Ag = A + (size_t)r * DD + kc;
    const float* Wg = W + (size_t)r * DD + kc;
    const uint32_t soff = (uint32_t)(r * BKP + kc) * 4;

    auto issue = [&](int stage, int it) {
        uint32_t sa = sbase + (uint32_t)stage * (STG_WORDS * 4) + soff;
        const float* ag = Ag + it * 16;
        const float* wg = Wg + it * 16;
#pragma unroll
        for (int p = 0; p < 4; p++) {
            cp16(sa + (uint32_t)(p * 32 * BKP) * 4,              ag + (size_t)(p * 32) * DD);
            cp16(sa + (uint32_t)(A_WORDS + p * 32 * BKP) * 4,    wg + (size_t)(p * 32) * DD);
        }
        asm volatile("cp.async.commit_group;");
    };

    float acc[4][8][4];
#pragma unroll
    for (int mi = 0; mi < 4; mi++)
#pragma unroll
        for (int nj = 0; nj < 8; nj++)
#pragma unroll
            for (int c = 0; c < 4; c++) acc[mi][nj][c] = 0.f;

    issue(0, 0);
    issue(1, 1);

    int stage = 0;
    for (int it = 0; it < KITERS; it++) {
        if (it + 2 < KITERS) {
            asm volatile("cp.async.wait_group 1;");
        } else {
            asm volatile("cp.async.wait_group 0;");
        }
        __syncthreads();
        if (it + 2 < KITERS) {
            int ns = stage + 2; if (ns >= NSTG) ns -= NSTG;
            issue(ns, it + 2);
        }
        const float* ab = smf + stage * STG_WORDS;
        const float* bb = ab + A_WORDS;

        // batch-load ALL fragments for both k=8 chunks, then mma
        uint32_t af[2][4][4], bf[2][8][2];
#pragma unroll
        for (int c = 0; c < 2; c++) {
            const int kk = c * 8;
#pragma unroll
            for (int mi = 0; mi < 4; mi++) {
                int row = wm * 64 + mi * 16 + g;
                af[c][mi][0] = f2tf32(ab[row * BKP + kk + t]);
                af[c][mi][1] = f2tf32(ab[(row + 8) * BKP + kk + t]);
                af[c][mi][2] = f2tf32(ab[row * BKP + kk + t + 4]);
                af[c][mi][3] = f2tf32(ab[(row + 8) * BKP + kk + t + 4]);
            }
#pragma unroll
            for (int nj = 0; nj < 8; nj++) {
                int rb = wn * 64 + nj * 8 + g;
                bf[c][nj][0] = f2tf32(bb[rb * BKP + kk + t]);
                bf[c][nj][1] = f2tf32(bb[rb * BKP + kk + t + 4]);
            }
        }
#pragma unroll
        for (int c = 0; c < 2; c++)
#pragma unroll
            for (int mi = 0; mi < 4; mi++)
#pragma unroll
                for (int nj = 0; nj < 8; nj++)
                    mma_tf32(acc[mi][nj],
                             af[c][mi][0], af[c][mi][1], af[c][mi][2], af[c][mi][3],
                             bf[c][nj][0], bf[c][nj][1]);

        stage++; if (stage >= NSTG) stage = 0;
    }

#pragma unroll
    for (int mi = 0; mi < 4; mi++) {
        int row = wm * 64 + mi * 16 + g;
#pragma unroll
        for (int nj = 0; nj < 8; nj++) {
            int col = wn * 64 + nj * 8 + 2 * t;
            float b0 = bias ? bias[col] : 0.f;
            float b1 = bias ? bias[col + 1] : 0.f;
            *(float2*)(C + (size_t)row * ldc + col) =
                make_float2(acc[mi][nj][0] + b0, acc[mi][nj][1] + b1);
            *(float2*)(C + (size_t)(row + 8) * ldc + col) =
                make_float2(acc[mi][nj][2] + b0, acc[mi][nj][3] + b1);
        }
    }
}

// Fused QKV projection: grid (32, 36). by<28 -> Q, <32 -> K, else V.
__global__ __launch_bounds__(128, 2) void qkv_kernel(
    const float* __restrict__ x,
    const float* __restrict__ wq, const float* __restrict__ bq,
    const float* __restrict__ wk, const float* __restrict__ bk,
    const float* __restrict__ wv, const float* __restrict__ bv)
{
    int m0 = blockIdx.x * 128;
    int by = blockIdx.y;
    const float* W; const float* bias; float* C; int ldc;
    if (by < 28) {
        W = wq + (size_t)by * 128 * DD;  bias = bq + by * 128;
        C = g_q + (size_t)m0 * DD + by * 128; ldc = DD;
    } else if (by < 32) {
        int nb = by - 28;
        W = wk + (size_t)nb * 128 * DD;  bias = bk + nb * 128;
        C = g_k + (size_t)m0 * 512 + nb * 128; ldc = 512;
    } else {
        int nb = by - 32;
        W = wv + (size_t)nb * 128 * DD;  bias = bv + nb * 128;
        C = g_v + (size_t)m0 * 512 + nb * 128; ldc = 512;
    }
    gemm_tile(x + (size_t)m0 * DD, W, bias, C, ldc);
}

// Output projection: grid (32, 28).
__global__ __launch_bounds__(128, 2) void oproj_kernel(
    const float* __restrict__ wo, float* __restrict__ out)
{
    int m0 = blockIdx.x * 128;
    int n0 = blockIdx.y * 128;
    gemm_tile(g_o + (size_t)m0 * DD, wo + (size_t)n0 * DD, nullptr,
              out + (size_t)m0 * DD + n0, DD);
}

// =====================================================================
// RoPE on g_q and g_k (in place).
// =====================================================================
__global__ __launch_bounds__(256) void rope_kernel(
    const float* __restrict__ cosT, const float* __restrict__ sinT,
    const int* __restrict__ spp)
{
    const int QP = MM * HH * 64;
    const int KP = MM * KVH * 64;
    int idx = blockIdx.x * blockDim.x + threadIdx.x;
    if (idx >= QP + KP) return;
    int sp = spp[0];
    float* buf; int nh; int i2;
    if (idx < QP) { buf = g_q; nh = HH;  i2 = idx; }
    else          { buf = g_k; nh = KVH; i2 = idx - QP; }
    int d2 = i2 & 63;
    int t  = i2 >> 6;
    int h  = t % nh;
    int m  = t / nh;
    int s  = m & (SS - 1);
    int pos = sp + s;
    float c  = cosT[pos * 64 + d2];
    float sn = sinT[pos * 64 + d2];
    size_t off = (size_t)m * (nh * HDIM) + h * HDIM + 2 * d2;
    float2 v = *(float2*)(buf + off);
    float yr = v.x * c - v.y * sn;
    float yi = v.x * sn + v.y * c;
    *(float2*)(buf + off) = make_float2(yr, yi);
}

// =====================================================================
// Flash attention (causal), fp32. BM=128, BN=64, HD=128, 256 thr (16x16),
// 8x4 S-microtile, 8x8 O-microtile, online softmax. smem ~166 KB.
// (At fp32-FMA roofline; unchanged this round.)
// =====================================================================
#define QTP 132
#define KTP 68
#define ATTN_SMEM_WORDS (128*QTP + 128*KTP + 64*128 + 128*KTP)
#define ATTN_SMEM_BYTES (ATTN_SMEM_WORDS*4)   // 169984

__global__ __launch_bounds__(256) void attn_kernel()
{
    extern __shared__ float sm[];
    float* Qt = sm;                       // [128 d][132 rows]
    float* Kt = Qt + 128*QTP;             // [128 d][68 rows]
    float* Vs = Kt + 128*KTP;             // [64 rows][128 d]
    float* Ps = Vs + 64*128;              // [128 rows][68 cols]

    const int qt = gridDim.x - 1 - blockIdx.x;    // heavy-first
    const int h  = blockIdx.y;
    const int b  = blockIdx.z;
    const int kvh = h / NREP;
    const int tid = threadIdx.x;
    const int ty = tid >> 4, tx = tid & 15;

    const int qrow0 = b * SS + qt * 128;

    {
        const float* qbase = g_q + (size_t)qrow0 * DD + h * HDIM;
#pragma unroll
        for (int tt = 0; tt < 16; tt++) {
            int f4 = tid + tt * 256;
            int row = f4 >> 5, d4 = f4 & 31;
            float4 qv = *(const float4*)(qbase + (size_t)row * DD + d4 * 4);
            Qt[(d4*4+0)*QTP + row] = qv.x;
            Qt[(d4*4+1)*QTP + row] = qv.y;
            Qt[(d4*4+2)*QTP + row] = qv.z;
            Qt[(d4*4+3)*QTP + row] = qv.w;
        }
    }

    float m_i[8], l_i[8], o_acc[8][8];
#pragma unroll
    for (int i = 0; i < 8; i++) {
        m_i[i] = -1e30f; l_i[i] = 0.f;
#pragma unroll
        for (int c = 0; c < 8; c++) o_acc[i][c] = 0.f;
    }

    const int ntmax = 2 * qt + 1;
    for (int nt = 0; nt <= ntmax; nt++) {
        const float* kb = g_k + (size_t)(b * SS + nt * 64) * 512 + kvh * HDIM;
        const float* vb = g_v + (size_t)(b * SS + nt * 64) * 512 + kvh * HDIM;

        __syncthreads();
#pragma unroll
        for (int tt = 0; tt < 8; tt++) {
            int f4 = tid + tt * 256;
            int row = f4 >> 5, d4 = f4 & 31;
            float4 k4 = *(const float4*)(kb + (size_t)row * 512 + d4 * 4);
            Kt[(d4*4+0)*KTP + row] = k4.x;
            Kt[(d4*4+1)*KTP + row] = k4.y;
            Kt[(d4*4+2)*KTP + row] = k4.z;
            Kt[(d4*4+3)*KTP + row] = k4.w;
            *(float4*)&Vs[row * 128 + d4 * 4] =
                *(const float4*)(vb + (size_t)row * 512 + d4 * 4);
        }
        __syncthreads();

        float s[8][4];
#pragma unroll
        for (int i = 0; i < 8; i++)
#pragma unroll
            for (int j = 0; j < 4; j++) s[i][j] = 0.f;

#pragma unroll 4
        for (int d = 0; d < 128; d++) {
            float4 q0 = *(const float4*)&Qt[d*QTP + ty*8];
            float4 q1 = *(const float4*)&Qt[d*QTP + ty*8 + 4];
            float4 kv = *(const float4*)&Kt[d*KTP + tx*4];
            float qa[8] = {q0.x,q0.y,q0.z,q0.w, q1.x,q1.y,q1.z,q1.w};
            float ka[4] = {kv.x,kv.y,kv.z,kv.w};
#pragma unroll
            for (int i = 0; i < 8; i++)
#pragma unroll
                for (int j = 0; j < 4; j++)
                    s[i][j] = fmaf(qa[i], ka[j], s[i][j]);
        }

        const bool edge = (nt >= 2 * qt);
        const int colbase = (nt - 2 * qt) * 64 + tx * 4;

#pragma unroll
        for (int i = 0; i < 8; i++) {
            int lrow = ty * 8 + i;
#pragma unroll
            for (int j = 0; j < 4; j++) {
                float val = s[i][j] * QK_SCALE;
                if (edge && (colbase + j > lrow)) val = -1e30f;
                s[i][j] = val;
            }
            float mt = fmaxf(fmaxf(s[i][0], s[i][1]), fmaxf(s[i][2], s[i][3]));
#pragma unroll
            for (int off = 8; off > 0; off >>= 1)
                mt = fmaxf(mt, __shfl_xor_sync(0xffffffffu, mt, off));
            float mnew  = fmaxf(m_i[i], mt);
            float alpha = __expf(m_i[i] - mnew);
            m_i[i] = mnew;
            float p0 = __expf(s[i][0] - mnew);
            float p1 = __expf(s[i][1] - mnew);
            float p2 = __expf(s[i][2] - mnew);
            float p3 = __expf(s[i][3] - mnew);
            float rs = (p0 + p1) + (p2 + p3);
#pragma unroll
            for (int off = 8; off > 0; off >>= 1)
                rs += __shfl_xor_sync(0xffffffffu, rs, off);
            l_i[i] = l_i[i] * alpha + rs;
#pragma unroll
            for (int c = 0; c < 8; c++) o_acc[i][c] *= alpha;
            int pr = lrow * KTP + tx * 4;
            Ps[pr+0] = p0; Ps[pr+1] = p1; Ps[pr+2] = p2; Ps[pr+3] = p3;
        }
        __syncthreads();

#pragma unroll 2
        for (int kc = 0; kc < 64; kc++) {
            float4 va = *(const float4*)&Vs[kc*128 + tx*4];
            float4 vb4 = *(const float4*)&Vs[kc*128 + 64 + tx*4];
#pragma unroll
            for (int i = 0; i < 8; i++) {
                float pp = Ps[(ty*8+i)*KTP + kc];
                o_acc[i][0] = fmaf(pp, va.x,  o_acc[i][0]);
                o_acc[i][1] = fmaf(pp, va.y,  o_acc[i][1]);
                o_acc[i][2] = fmaf(pp, va.z,  o_acc[i][2]);
                o_acc[i][3] = fmaf(pp, va.w,  o_acc[i][3]);
                o_acc[i][4] = fmaf(pp, vb4.x, o_acc[i][4]);
                o_acc[i][5] = fmaf(pp, vb4.y, o_acc[i][5]);
                o_acc[i][6] = fmaf(pp, vb4.z, o_acc[i][6]);
                o_acc[i][7] = fmaf(pp, vb4.w, o_acc[i][7]);
            }
        }
    }

    float* obase = g_o + (size_t)qrow0 * DD + h * HDIM;
#pragma unroll
    for (int i = 0; i < 8; i++) {
        int r = ty * 8 + i;
        float inv = 1.0f / l_i[i];
        float4 r0 = make_float4(o_acc[i][0]*inv, o_acc[i][1]*inv,
                                o_acc[i][2]*inv, o_acc[i][3]*inv);
        float4 r1 = make_float4(o_acc[i][4]*inv, o_acc[i][5]*inv,
                                o_acc[i][6]*inv, o_acc[i][7]*inv);
        *(float4*)(obase + (size_t)r * DD + tx*4)      = r0;
        *(float4*)(obase + (size_t)r * DD + 64 + tx*4) = r1;
    }
}

// =====================================================================
// launch
// =====================================================================
extern "C" void kernel_launch(void* const* d_in, const int* in_sizes, int n_in,
                              void* d_out, int out_size)
{
    const float* x    = (const float*)d_in[0];
    const float* wq_w = (const float*)d_in[1];
    const float* wq_b = (const float*)d_in[2];
    const float* wk_w = (const float*)d_in[3];
    const float* wk_b = (const float*)d_in[4];
    const float* wv_w = (const float*)d_in[5];
    const float* wv_b = (const float*)d_in[6];
    const float* wo_w = (const float*)d_in[7];
    const float* fcos = (const float*)d_in[10];
    const float* fsin = (const float*)d_in[11];
    const int*   spos = (const int*)d_in[13];
    float* out = (float*)d_out;

    cudaFuncSetAttribute(qkv_kernel,
                         cudaFuncAttributeMaxDynamicSharedMemorySize, GEMM_SMEM_BYTES);
    cudaFuncSetAttribute(oproj_kernel,
                         cudaFuncAttributeMaxDynamicSharedMemorySize, GEMM_SMEM_BYTES);
    cudaFuncSetAttribute(attn_kernel,
                         cudaFuncAttributeMaxDynamicSharedMemorySize, ATTN_SMEM_BYTES);

    qkv_kernel<<<dim3(32, 36), 128, GEMM_SMEM_BYTES>>>(
        x, wq_w, wq_b, wk_w, wk_b, wv_w, wv_b);

    int pairs = MM * HH * 64 + MM * KVH * 64;
    rope_kernel<<<(pairs + 255) / 256, 256>>>(fcos, fsin, spos);

    attn_kernel<<<dim3(16, 28, 2), 256, ATTN_SMEM_BYTES>>>();

    oproj_kernel<<<dim3(32, 28), 128, GEMM_SMEM_BYTES>>>(wo_w, out);
}